// round 13
// baseline (speedup 1.0000x reference)
#include <cuda_runtime.h>

#define B   8
#define C   1024
#define HW  4096
#define K   16

// Scratch (no allocations allowed) — fully rewritten every launch.
__device__ float g_num[B * K * C];      // masked class sums
__device__ float g_protoN[B * K * C];   // prototypes / (count * ||proto||)
__device__ int   g_counts[B * (K + 1)]; // per-class pixel counts (incl. class 0)

// ---------------------------------------------------------------------------
// K2: masked per-class sums + fused per-batch histogram (blockIdx.x==0).
// One warp = one channel; lane-private smem slots acc[class][tid]
// (bank = tid%32 -> conflict-free dynamic indexing).  4 float4 in flight.
// ---------------------------------------------------------------------------
__global__ void __launch_bounds__(256) proto_sum_kernel(
        const float* __restrict__ feat, const int* __restrict__ masks) {
    __shared__ unsigned char cls[HW];       // 4 KB
    __shared__ float acc[K][256];           // 16 KB
    __shared__ int   h[K + 1];

    const int b    = blockIdx.y;
    const int tid  = threadIdx.x;
    const int warp = tid >> 5;
    const int lane = tid & 31;
    const int c    = blockIdx.x * 8 + warp;

#pragma unroll
    for (int k = 0; k < K; k++) acc[k][tid] = 0.0f;
    if (tid <= K) h[tid] = 0;
    for (int p = tid; p < HW; p += 256) {
        int v = masks[b * HW + p];
        cls[p] = (unsigned char)((v >= 1 && v <= K) ? v : 0);  // guarded
    }
    __syncthreads();

    // fused histogram: only the x==0 blocks do it (hidden under DRAM traffic)
    if (blockIdx.x == 0) {
        for (int p = tid; p < HW; p += 256) atomicAdd(&h[cls[p]], 1);
    }

    const float4* f4 = (const float4*)(feat + ((size_t)b * C + c) * HW);
    const uchar4* c4 = (const uchar4*)cls;

    for (int i = lane; i < HW / 4; i += 128) {
        float4 v0 = f4[i];
        float4 v1 = f4[i + 32];
        float4 v2 = f4[i + 64];
        float4 v3 = f4[i + 96];
        uchar4 m0 = c4[i];
        uchar4 m1 = c4[i + 32];
        uchar4 m2 = c4[i + 64];
        uchar4 m3 = c4[i + 96];
        if (m0.x) acc[m0.x - 1][tid] += v0.x;
        if (m0.y) acc[m0.y - 1][tid] += v0.y;
        if (m0.z) acc[m0.z - 1][tid] += v0.z;
        if (m0.w) acc[m0.w - 1][tid] += v0.w;
        if (m1.x) acc[m1.x - 1][tid] += v1.x;
        if (m1.y) acc[m1.y - 1][tid] += v1.y;
        if (m1.z) acc[m1.z - 1][tid] += v1.z;
        if (m1.w) acc[m1.w - 1][tid] += v1.w;
        if (m2.x) acc[m2.x - 1][tid] += v2.x;
        if (m2.y) acc[m2.y - 1][tid] += v2.y;
        if (m2.z) acc[m2.z - 1][tid] += v2.z;
        if (m2.w) acc[m2.w - 1][tid] += v2.w;
        if (m3.x) acc[m3.x - 1][tid] += v3.x;
        if (m3.y) acc[m3.y - 1][tid] += v3.y;
        if (m3.z) acc[m3.z - 1][tid] += v3.z;
        if (m3.w) acc[m3.w - 1][tid] += v3.w;
    }

#pragma unroll
    for (int k = 0; k < K; k++) {
        float s = acc[k][tid];
#pragma unroll
        for (int off = 16; off; off >>= 1)
            s += __shfl_down_sync(0xffffffffu, s, off);
        if (lane == 0) g_num[((size_t)b * K + k) * C + c] = s;
    }

    if (blockIdx.x == 0) {
        __syncthreads();
        if (tid <= K) g_counts[b * (K + 1) + tid] = h[tid];
    }
}

// ---------------------------------------------------------------------------
// K3: g_protoN = (num/count) / ||num/count||.
// argmax_k dot(protoN_k, q) == argmax_k cosine_sim.
// ---------------------------------------------------------------------------
__global__ void __launch_bounds__(256) finalize_kernel() {
    const int b = blockIdx.y, k = blockIdx.x, tid = threadIdx.x;
    const int cnt = g_counts[b * (K + 1) + k + 1];
    const float invCnt = cnt > 0 ? 1.0f / (float)cnt : 0.0f;
    const float* num = g_num    + ((size_t)(b * K + k)) * C;
    float*       out = g_protoN + ((size_t)(b * K + k)) * C;

    float pv[4];
    float ss = 0.0f;
#pragma unroll
    for (int j = 0; j < 4; j++) {
        pv[j] = num[tid + j * 256] * invCnt;
        ss += pv[j] * pv[j];
    }

    __shared__ float red[8];
    __shared__ float s_inv;
#pragma unroll
    for (int off = 16; off; off >>= 1)
        ss += __shfl_down_sync(0xffffffffu, ss, off);
    if ((tid & 31) == 0) red[tid >> 5] = ss;
    __syncthreads();
    if (tid == 0) {
        float s = 0.0f;
#pragma unroll
        for (int w = 0; w < 8; w++) s += red[w];
        s_inv = s > 0.0f ? 1.0f / sqrtf(s) : 0.0f;
    }
    __syncthreads();
    const float inv = s_inv;
#pragma unroll
    for (int j = 0; j < 4; j++) out[tid + j * 256] = pv[j] * inv;
}

// ---------------------------------------------------------------------------
// K4: pixel-packed match, deep software pipeline.
// Thread = (slice, t): slice = (k_half, ch_quarter), t covers 4 consecutive
// pixels; q read via LDG.128 over pixels.  8-channel batches double-buffered:
// 8 LDG.128 (1 KB/warp) in flight while the previous 8 channels compute —
// 16 KB/SM outstanding > the ~11.4 KB needed for full DRAM bandwidth.
// __launch_bounds__(256, 2): 2 CTAs/SM guaranteed, 128-reg budget.
// Reduction order identical to R11.
// ---------------------------------------------------------------------------
__device__ __forceinline__ void fma_batch(
        const float* __restrict__ spb, int c,
        const float4& v0, const float4& v1, const float4& v2, const float4& v3,
        unsigned long long (&acc2)[8][2]) {
    const ulonglong2 u0 = *(const ulonglong2*)&v0;   // (p0,p1),(p2,p3)
    const ulonglong2 u1 = *(const ulonglong2*)&v1;
    const ulonglong2 u2 = *(const ulonglong2*)&v2;
    const ulonglong2 u3 = *(const ulonglong2*)&v3;
#pragma unroll
    for (int kk = 0; kk < 8; kk++) {
        const float4 pk = *(const float4*)(spb + kk * C + c);  // LDS.128 bcast
        unsigned long long d0, d1, d2, d3;
        asm("mov.b64 %0, {%1, %1};" : "=l"(d0) : "f"(pk.x));
        asm("mov.b64 %0, {%1, %1};" : "=l"(d1) : "f"(pk.y));
        asm("mov.b64 %0, {%1, %1};" : "=l"(d2) : "f"(pk.z));
        asm("mov.b64 %0, {%1, %1};" : "=l"(d3) : "f"(pk.w));
        asm("fma.rn.f32x2 %0, %1, %2, %0;" : "+l"(acc2[kk][0]) : "l"(u0.x), "l"(d0));
        asm("fma.rn.f32x2 %0, %1, %2, %0;" : "+l"(acc2[kk][1]) : "l"(u0.y), "l"(d0));
        asm("fma.rn.f32x2 %0, %1, %2, %0;" : "+l"(acc2[kk][0]) : "l"(u1.x), "l"(d1));
        asm("fma.rn.f32x2 %0, %1, %2, %0;" : "+l"(acc2[kk][1]) : "l"(u1.y), "l"(d1));
        asm("fma.rn.f32x2 %0, %1, %2, %0;" : "+l"(acc2[kk][0]) : "l"(u2.x), "l"(d2));
        asm("fma.rn.f32x2 %0, %1, %2, %0;" : "+l"(acc2[kk][1]) : "l"(u2.y), "l"(d2));
        asm("fma.rn.f32x2 %0, %1, %2, %0;" : "+l"(acc2[kk][0]) : "l"(u3.x), "l"(d3));
        asm("fma.rn.f32x2 %0, %1, %2, %0;" : "+l"(acc2[kk][1]) : "l"(u3.y), "l"(d3));
    }
}

__device__ __forceinline__ void load8(const float* __restrict__ qb, int c,
                                      float4 (&buf)[8]) {
#pragma unroll
    for (int j = 0; j < 8; j++)
        buf[j] = *(const float4*)&qb[(size_t)(c + j) * HW];
}

__global__ void __launch_bounds__(256, 2) match_kernel(
        const float* __restrict__ q, float* __restrict__ out) {
    extern __shared__ __align__(16) char smem_raw[];
    float*              sp  = (float*)smem_raw;              // [K][C] = 64 KB
    unsigned long long* red = (unsigned long long*)smem_raw; // reuse: 32 KB

    const int b     = blockIdx.y;
    const int tid   = threadIdx.x;
    const int slice = tid >> 5;          // 0..7
    const int t     = tid & 31;          // 0..31
    const int kh    = slice & 1;         // protos [kh*8, kh*8+8)
    const int cq    = slice >> 1;        // channels [cq*256, cq*256+256)
    const int p     = blockIdx.x * 128 + t * 4;   // 4 consecutive pixels

    // stage all 16x1024 normalized prototypes
    const float4* pr4 = (const float4*)(g_protoN + (size_t)b * K * C);
    for (int i = tid; i < K * C / 4; i += 256)
        ((float4*)sp)[i] = pr4[i];
    __syncthreads();

    const float* qb  = q + ((size_t)b * C + cq * 256) * HW + p;
    const float* spb = sp + (kh * 8) * C + cq * 256;

    unsigned long long acc2[8][2];   // [kk][pixel-pair]
#pragma unroll
    for (int kk = 0; kk < 8; kk++) { acc2[kk][0] = 0ull; acc2[kk][1] = 0ull; }

    float4 A[8], Bv[8];
    load8(qb, 0, A);                          // prologue: channels 0..7

#pragma unroll 2
    for (int c = 0; c < 256; c += 16) {
        load8(qb, c + 8, Bv);                 // 8 LDG.128 in flight over A's compute
        fma_batch(spb, c,     A[0], A[1], A[2], A[3], acc2);
        fma_batch(spb, c + 4, A[4], A[5], A[6], A[7], acc2);
        if (c + 16 < 256) load8(qb, c + 16, A);   // prefetch next A over B's compute
        fma_batch(spb, c +  8, Bv[0], Bv[1], Bv[2], Bv[3], acc2);
        fma_batch(spb, c + 12, Bv[4], Bv[5], Bv[6], Bv[7], acc2);
    }

    // protos dead -> partials in smem, lane-contiguous: red[k][pair][cs][t]
    __syncthreads();
#pragma unroll
    for (int kk = 0; kk < 8; kk++) {
        const int k = kh * 8 + kk;
        red[((k * 2 + 0) * 4 + cq) * 32 + t] = acc2[kk][0];
        red[((k * 2 + 1) * 4 + cq) * 32 + t] = acc2[kk][1];
    }
    __syncthreads();

    // one thread per pixel: sum 4 channel-quarters (packed), pick lane, argmax
    if (tid < 128) {
        const int tt   = tid >> 2;        // source thread
        const int pair = (tid >> 1) & 1;
        const int lohi = tid & 1;
        float best = -3.0e38f;
        int   bi   = 0;
#pragma unroll
        for (int k = 0; k < K; k++) {
            const unsigned long long* r = red + (k * 2 + pair) * 4 * 32 + tt;
            unsigned long long s01, s23, s;
            asm("add.rn.f32x2 %0, %1, %2;" : "=l"(s01) : "l"(r[0]),   "l"(r[32]));
            asm("add.rn.f32x2 %0, %1, %2;" : "=l"(s23) : "l"(r[64]),  "l"(r[96]));
            asm("add.rn.f32x2 %0, %1, %2;" : "=l"(s)   : "l"(s01),    "l"(s23));
            float lo, hi;
            asm("mov.b64 {%0, %1}, %2;" : "=f"(lo), "=f"(hi) : "l"(s));
            const float v = lohi ? hi : lo;
            if (v > best) { best = v; bi = k; }
        }
        out[(size_t)b * HW + blockIdx.x * 128 + tid] = (float)bi;  // f32 output
    }
}

// ---------------------------------------------------------------------------
extern "C" void kernel_launch(void* const* d_in, const int* in_sizes, int n_in,
                              void* d_out, int out_size) {
    // masks is the unique B*HW = 32768-element input; its position fixes the
    // ordering of the two feature tensors.
    int mask_idx = 1;
    for (int i = 0; i < n_in; i++)
        if (in_sizes[i] == B * HW) { mask_idx = i; break; }

    const int*   masks = (const int*)d_in[mask_idx];
    const float* sfeat;
    const float* qfeat;
    if (mask_idx == 1)      { sfeat = (const float*)d_in[0]; qfeat = (const float*)d_in[2]; }
    else if (mask_idx == 2) { qfeat = (const float*)d_in[0]; sfeat = (const float*)d_in[1]; }
    else                    { qfeat = (const float*)d_in[1]; sfeat = (const float*)d_in[2]; }
    float* out = (float*)d_out;
    (void)out_size;

    proto_sum_kernel<<<dim3(C / 8, B), 256>>>(sfeat, masks);
    finalize_kernel<<<dim3(K, B), 256>>>();

    static int smem_set = 0;
    if (!smem_set) {
        cudaFuncSetAttribute(match_kernel,
                             cudaFuncAttributeMaxDynamicSharedMemorySize,
                             K * C * (int)sizeof(float));
        smem_set = 1;
    }
    match_kernel<<<dim3(HW / 128, B), 256, K * C * sizeof(float)>>>(qfeat, out);
}